// round 14
// baseline (speedup 1.0000x reference)
#include <cuda_runtime.h>
#include <cstdint>

#define N_NODES 8192
#define N_EDGES 16384
#define E4      (N_EDGES / 4)      // 4096 float4 per matrix row
#define NCHUNK  64
#define ROWS_PB (N_NODES / NCHUNK) // 128 rows per gather block
#define K1_THREADS 128

// ---------------- scratch (device globals; no allocs allowed) ----------------
// Partial matrix-vector products: [NCHUNK][E4] float4 = 4 MB each. Fully
// overwritten every launch -> deterministic, no zeroing needed.
__device__ __align__(16) float4 g_ppo[(size_t)NCHUNK * E4];  // partial Ro^T u
__device__ __align__(16) float4 g_ppi[(size_t)NCHUNK * E4];  // partial Ri^T v
__device__ __align__(16) float  g_so[N_EDGES];
__device__ __align__(16) float  g_si[N_EDGES];

// ---------------- kernel 1: p = Ro^T u, q = Ri^T v (partials) -----------------
// Rank-1 restructure: u = X k[0:4], v = X k[4:8] computed per block in smem.
// Each thread owns 4 consecutive edges (one float4 per row per matrix) and
// accumulates just 2 float4 partials -> ~12 instrs per 32B, deep LDG staging.
__global__ __launch_bounds__(K1_THREADS)
void gather_kernel(const float4* __restrict__ X4,
                   const float4* __restrict__ Ri4,
                   const float4* __restrict__ Ro4,
                   const float* __restrict__ kern) {
    __shared__ float su[ROWS_PB];   // u = X·k[0:4]
    __shared__ float sv[ROWS_PB];   // v = X·k[4:8]

    const int n0 = blockIdx.y * ROWS_PB;
    for (int i = threadIdx.x; i < ROWS_PB; i += K1_THREADS) {
        float4 x = X4[n0 + i];
        su[i] = x.x * kern[0] + x.y * kern[1] + x.z * kern[2] + x.w * kern[3];
        sv[i] = x.x * kern[4] + x.y * kern[5] + x.z * kern[6] + x.w * kern[7];
    }
    __syncthreads();

    const int e4 = blockIdx.x * K1_THREADS + threadIdx.x;
    const float4* ro = Ro4 + (size_t)n0 * E4 + e4;
    const float4* ri = Ri4 + (size_t)n0 * E4 + e4;

    float4 po = make_float4(0.f, 0.f, 0.f, 0.f);
    float4 pi = make_float4(0.f, 0.f, 0.f, 0.f);

    #pragma unroll 8
    for (int nl = 0; nl < ROWS_PB; ++nl) {
        float4 r = ro[(size_t)nl * E4];
        float4 q = ri[(size_t)nl * E4];
        float u = su[nl], v = sv[nl];
        po.x += r.x * u; po.y += r.y * u; po.z += r.z * u; po.w += r.w * u;
        pi.x += q.x * v; pi.y += q.y * v; pi.z += q.z * v; pi.w += q.w * v;
    }

    g_ppo[(size_t)blockIdx.y * E4 + e4] = po;
    g_ppi[(size_t)blockIdx.y * E4 + e4] = pi;
}

// ---------------- kernel 2: reduce partials, so = e∘p, si = e∘q ---------------
__global__ __launch_bounds__(256)
void edge_kernel(const float4* __restrict__ ew4) {
    int e4 = blockIdx.x * blockDim.x + threadIdx.x;
    if (e4 >= E4) return;

    float4 po = make_float4(0.f, 0.f, 0.f, 0.f);
    float4 pi = make_float4(0.f, 0.f, 0.f, 0.f);
    #pragma unroll 8
    for (int c = 0; c < NCHUNK; ++c) {
        float4 a = g_ppo[(size_t)c * E4 + e4];
        po.x += a.x; po.y += a.y; po.z += a.z; po.w += a.w;
        float4 b = g_ppi[(size_t)c * E4 + e4];
        pi.x += b.x; pi.y += b.y; pi.z += b.z; pi.w += b.w;
    }

    float4 w = ew4[e4];
    float4* so4 = reinterpret_cast<float4*>(g_so);
    float4* si4 = reinterpret_cast<float4*>(g_si);
    so4[e4] = make_float4(w.x * po.x, w.y * po.y, w.z * po.z, w.w * po.w);
    si4[e4] = make_float4(w.x * pi.x, w.y * pi.y, w.z * pi.z, w.w * pi.w);
}

// ---------------- kernel 3: out[n] = Ri[n,:]·so + Ro[n,:]·si + X[n]·k[8:12] --
__global__ __launch_bounds__(256)
void scatter_kernel(const float4* __restrict__ Ri4,
                    const float4* __restrict__ Ro4,
                    const float4* __restrict__ X4,
                    const float* __restrict__ kern,
                    float* __restrict__ out) {
    const int n = blockIdx.x;
    const float4* ri = Ri4 + (size_t)n * E4;
    const float4* ro = Ro4 + (size_t)n * E4;
    const float4* so4 = reinterpret_cast<const float4*>(g_so);
    const float4* si4 = reinterpret_cast<const float4*>(g_si);

    float s = 0.0f;
    #pragma unroll 4
    for (int t = 0; t < E4 / 256; ++t) {
        int j = t * 256 + threadIdx.x;
        float4 a = ri[j], w = so4[j];
        s += a.x * w.x + a.y * w.y + a.z * w.z + a.w * w.w;
        float4 b = ro[j], v = si4[j];
        s += b.x * v.x + b.y * v.y + b.z * v.z + b.w * v.w;
    }

    #pragma unroll
    for (int off = 16; off > 0; off >>= 1)
        s += __shfl_down_sync(0xFFFFFFFFu, s, off);

    __shared__ float red[8];
    int wid = threadIdx.x >> 5, lid = threadIdx.x & 31;
    if (lid == 0) red[wid] = s;
    __syncthreads();
    if (wid == 0) {
        s = (lid < 8) ? red[lid] : 0.0f;
        #pragma unroll
        for (int off = 4; off > 0; off >>= 1)
            s += __shfl_down_sync(0xFFFFFFFFu, s, off);
        if (lid == 0) {
            float4 x = X4[n];
            s += x.x * kern[8] + x.y * kern[9] + x.z * kern[10] + x.w * kern[11];
            out[n] = s;
        }
    }
}

// ---------------- launch ------------------------------------------------------
extern "C" void kernel_launch(void* const* d_in, const int* in_sizes, int n_in,
                              void* d_out, int out_size) {
    const float* X    = (const float*)d_in[0];   // [8192, 4]
    const float* e    = (const float*)d_in[1];   // [16384, 1]
    const float* Ri   = (const float*)d_in[2];   // [8192, 16384]
    const float* Ro   = (const float*)d_in[3];   // [8192, 16384]
    const float* kern = (const float*)d_in[4];   // [12, 1]
    float* out = (float*)d_out;                  // [8192, 1]

    gather_kernel<<<dim3(E4 / K1_THREADS, NCHUNK), K1_THREADS>>>(
        (const float4*)X, (const float4*)Ri, (const float4*)Ro, kern);
    edge_kernel<<<E4 / 256, 256>>>((const float4*)e);
    scatter_kernel<<<N_NODES, 256>>>(
        (const float4*)Ri, (const float4*)Ro, (const float4*)X, kern, out);
}

// round 17
// speedup vs baseline: 1.0061x; 1.0061x over previous
#include <cuda_runtime.h>
#include <cstdint>

#define N_NODES 8192
#define N_EDGES 16384
#define E4      (N_EDGES / 4)      // 4096 float4 per matrix row
#define NCHUNK  64
#define ROWS_PB (N_NODES / NCHUNK) // 128 rows per gather block
#define K1_THREADS 256

// ---------------- scratch (device globals; no allocs allowed) ----------------
// Partial matrix-vector products: [NCHUNK][E4] float4 = 4 MB each. Fully
// overwritten every launch -> deterministic, no zeroing needed.
__device__ __align__(16) float4 g_ppo[(size_t)NCHUNK * E4];  // partial Ro^T u
__device__ __align__(16) float4 g_ppi[(size_t)NCHUNK * E4];  // partial Ri^T v
__device__ __align__(16) float  g_so[N_EDGES];
__device__ __align__(16) float  g_si[N_EDGES];

// ---------------- kernel 1: p = Ro^T u, q = Ri^T v (partials) -----------------
// Rank-1 gather: u = X k[0:4], v = X k[4:8] in smem; each thread owns one
// float4 of edges, 2 float4 accumulators. 256-thread blocks -> each block
// reads 4 KB contiguous per matrix per row (DRAM page locality) and the
// grid (16 x 64 = 1024 blocks) gives ~55 warps/SM for latency hiding.
__global__ __launch_bounds__(K1_THREADS)
void gather_kernel(const float4* __restrict__ X4,
                   const float4* __restrict__ Ri4,
                   const float4* __restrict__ Ro4,
                   const float* __restrict__ kern) {
    __shared__ float su[ROWS_PB];   // u = X·k[0:4]
    __shared__ float sv[ROWS_PB];   // v = X·k[4:8]

    const int n0 = blockIdx.y * ROWS_PB;
    for (int i = threadIdx.x; i < ROWS_PB; i += K1_THREADS) {
        float4 x = X4[n0 + i];
        su[i] = x.x * kern[0] + x.y * kern[1] + x.z * kern[2] + x.w * kern[3];
        sv[i] = x.x * kern[4] + x.y * kern[5] + x.z * kern[6] + x.w * kern[7];
    }
    __syncthreads();

    const int e4 = blockIdx.x * K1_THREADS + threadIdx.x;
    const float4* ro = Ro4 + (size_t)n0 * E4 + e4;
    const float4* ri = Ri4 + (size_t)n0 * E4 + e4;

    float4 po = make_float4(0.f, 0.f, 0.f, 0.f);
    float4 pi = make_float4(0.f, 0.f, 0.f, 0.f);

    #pragma unroll 8
    for (int nl = 0; nl < ROWS_PB; ++nl) {
        float4 r = ro[(size_t)nl * E4];
        float4 q = ri[(size_t)nl * E4];
        float u = su[nl], v = sv[nl];
        po.x += r.x * u; po.y += r.y * u; po.z += r.z * u; po.w += r.w * u;
        pi.x += q.x * v; pi.y += q.y * v; pi.z += q.z * v; pi.w += q.w * v;
    }

    g_ppo[(size_t)blockIdx.y * E4 + e4] = po;
    g_ppi[(size_t)blockIdx.y * E4 + e4] = pi;
}

// ---------------- kernel 2: reduce partials, so = e∘p, si = e∘q ---------------
__global__ __launch_bounds__(256)
void edge_kernel(const float4* __restrict__ ew4) {
    int e4 = blockIdx.x * blockDim.x + threadIdx.x;
    if (e4 >= E4) return;

    float4 po = make_float4(0.f, 0.f, 0.f, 0.f);
    float4 pi = make_float4(0.f, 0.f, 0.f, 0.f);
    #pragma unroll 8
    for (int c = 0; c < NCHUNK; ++c) {
        float4 a = g_ppo[(size_t)c * E4 + e4];
        po.x += a.x; po.y += a.y; po.z += a.z; po.w += a.w;
        float4 b = g_ppi[(size_t)c * E4 + e4];
        pi.x += b.x; pi.y += b.y; pi.z += b.z; pi.w += b.w;
    }

    float4 w = ew4[e4];
    float4* so4 = reinterpret_cast<float4*>(g_so);
    float4* si4 = reinterpret_cast<float4*>(g_si);
    so4[e4] = make_float4(w.x * po.x, w.y * po.y, w.z * po.z, w.w * po.w);
    si4[e4] = make_float4(w.x * pi.x, w.y * pi.y, w.z * pi.z, w.w * pi.w);
}

// ---------------- kernel 3: out[n] = Ri[n,:]·so + Ro[n,:]·si + X[n]·k[8:12] --
__global__ __launch_bounds__(256)
void scatter_kernel(const float4* __restrict__ Ri4,
                    const float4* __restrict__ Ro4,
                    const float4* __restrict__ X4,
                    const float* __restrict__ kern,
                    float* __restrict__ out) {
    const int n = blockIdx.x;
    const float4* ri = Ri4 + (size_t)n * E4;
    const float4* ro = Ro4 + (size_t)n * E4;
    const float4* so4 = reinterpret_cast<const float4*>(g_so);
    const float4* si4 = reinterpret_cast<const float4*>(g_si);

    float s = 0.0f;
    #pragma unroll 4
    for (int t = 0; t < E4 / 256; ++t) {
        int j = t * 256 + threadIdx.x;
        float4 a = ri[j], w = so4[j];
        s += a.x * w.x + a.y * w.y + a.z * w.z + a.w * w.w;
        float4 b = ro[j], v = si4[j];
        s += b.x * v.x + b.y * v.y + b.z * v.z + b.w * v.w;
    }

    #pragma unroll
    for (int off = 16; off > 0; off >>= 1)
        s += __shfl_down_sync(0xFFFFFFFFu, s, off);

    __shared__ float red[8];
    int wid = threadIdx.x >> 5, lid = threadIdx.x & 31;
    if (lid == 0) red[wid] = s;
    __syncthreads();
    if (wid == 0) {
        s = (lid < 8) ? red[lid] : 0.0f;
        #pragma unroll
        for (int off = 4; off > 0; off >>= 1)
            s += __shfl_down_sync(0xFFFFFFFFu, s, off);
        if (lid == 0) {
            float4 x = X4[n];
            s += x.x * kern[8] + x.y * kern[9] + x.z * kern[10] + x.w * kern[11];
            out[n] = s;
        }
    }
}

// ---------------- launch ------------------------------------------------------
extern "C" void kernel_launch(void* const* d_in, const int* in_sizes, int n_in,
                              void* d_out, int out_size) {
    const float* X    = (const float*)d_in[0];   // [8192, 4]
    const float* e    = (const float*)d_in[1];   // [16384, 1]
    const float* Ri   = (const float*)d_in[2];   // [8192, 16384]
    const float* Ro   = (const float*)d_in[3];   // [8192, 16384]
    const float* kern = (const float*)d_in[4];   // [12, 1]
    float* out = (float*)d_out;                  // [8192, 1]

    gather_kernel<<<dim3(E4 / K1_THREADS, NCHUNK), K1_THREADS>>>(
        (const float4*)X, (const float4*)Ri, (const float4*)Ro, kern);
    edge_kernel<<<E4 / 256, 256>>>((const float4*)e);
    scatter_kernel<<<N_NODES, 256>>>(
        (const float4*)Ri, (const float4*)Ro, (const float4*)X, kern, out);
}